// round 5
// baseline (speedup 1.0000x reference)
#include <cuda_runtime.h>
#include <cstdint>

#define TMAX 1280

__device__ int g_lab[TMAX];        // fallback path only
__device__ float4 g_txyxy[TMAX];   // fallback path only
__device__ float2 g_tal[TMAX];     // fallback path only

__device__ __forceinline__ float frcp(float x) {
    float r;
    asm("rcp.approx.f32 %0, %1;" : "=f"(r) : "f"(x));
    return r;
}

// Fallback-path setup: label normalize + target xyxy/area precompute.
__global__ void setup_kernel(const float4* __restrict__ tboxes,
                             const int* __restrict__ lraw, int m) {
    __shared__ int is64;
    if (threadIdx.x == 0) is64 = 1;
    __syncthreads();
    for (int t = threadIdx.x; t < m / 2; t += blockDim.x)
        if (lraw[2 * t + 1] != 0) is64 = 0;
    __syncthreads();
    int f = is64;
    for (int j = threadIdx.x; j < m; j += blockDim.x) {
        int lab = f ? lraw[2 * j] : lraw[j];
        g_lab[j] = lab;
        float4 b = tboxes[j];
        float hw = 0.5f * b.z, hh = 0.5f * b.w;
        float4 t;
        t.x = b.x - hw; t.y = b.y - hh;
        t.z = b.x + hw; t.w = b.y + hh;
        g_txyxy[j] = t;
        float2 al;
        al.x = (t.z - t.x) * (t.w - t.y);
        al.y = __int_as_float(lab);
        g_tal[j] = al;
    }
}

// ---------------------------------------------------------------------------
// Fast-path tile body, templated on label stride (SH=1: int64, SH=0: int32).
// Thread owns 4 rows x 20 column steps; all offsets immediate.
// ---------------------------------------------------------------------------
template <int SH>
__device__ __forceinline__ void cost_tile(
    const float* __restrict__ sp,        // scores + row0*C
    float* __restrict__ op,              // out + row0*M + tx
    const float4* __restrict__ tb,       // tboxes + tx
    const int* __restrict__ lp,          // lraw + (tx << SH)
    const float qcx[4], const float qcy[4],
    const float qwz[4], const float qwh[4],
    const float qx0[4], const float qy0[4],
    const float qx1[4], const float qy1[4],
    const float qa[4])
{
    constexpr int C = 91;
    constexpr int M = 1280;

#pragma unroll 10
    for (int jj = 0; jj < 20; jj++) {
        float4 b = __ldg(tb + jj * 64);          // target cxcywh
        int lab = __ldg(lp + ((jj * 64) << SH)); // immediate-offset label
        float hw = 0.5f * b.z, hh = 0.5f * b.w;
        float tx0 = b.x - hw, ty0 = b.y - hh;
        float tx1 = b.x + hw, ty1 = b.y + hh;
        float ta = b.z * b.w;
        const float* sa = sp + lab;

        float scv[4];
#pragma unroll
        for (int k = 0; k < 4; k++) scv[k] = __ldg(sa + k * C);

#pragma unroll
        for (int k = 0; k < 4; k++) {
            // L1 on raw cxcywh (exact vs reference; abs folds into operands)
            float ux = qcx[k] - b.x, uy = qcy[k] - b.y;
            float vx = qwz[k] - b.z, vy = qwh[k] - b.w;
            float l1 = (fabsf(ux) + fabsf(uy)) + (fabsf(vx) + fabsf(vy));

            // signed per-dim overlap; reused for intersection and enclosure
            float ox = fminf(qx1[k], tx1) - fmaxf(qx0[k], tx0);
            float oy = fminf(qy1[k], ty1) - fmaxf(qy0[k], ty0);
            float iw = fmaxf(ox, 0.0f), ih = fmaxf(oy, 0.0f);
            float inter = iw * ih;

            // enclosing box: span = w + w' - signed_overlap
            float ew = (qwz[k] + b.z) - ox;
            float eh = (qwh[k] + b.w) - oy;
            float ae = ew * eh;

            float uni = (qa[k] + ta) - inter;

            // cost = 5*l1 + (2 - sc) - 2*(inter/uni + uni/ae)
            float s = fmaf(uni, frcp(ae), inter * frcp(uni));
            float c = fmaf(5.0f, l1, 2.0f - scv[k]);
            c = fmaf(-2.0f, s, c);

            op[k * M + jj * 64] = c;
        }
    }
}

// ---------------------------------------------------------------------------
// Fast path: C=91, M=1280, rows % 8 == 0.
// 128-thread blocks = 8 rows x 64 lanes; 8 blocks/SM -> 1184-slot capacity,
// grid=1200 -> fine-grained wave edge. Single launch (in-block label probe).
// ---------------------------------------------------------------------------
__global__ void __launch_bounds__(128, 8)
cost_kernel_fast(const float* __restrict__ scores,
                 const float4* __restrict__ boxes,
                 const int* __restrict__ lraw,
                 const float4* __restrict__ tboxes,
                 float* __restrict__ out) {
    constexpr int C = 91;
    constexpr int M = 1280;

    int tid = threadIdx.x;
    int tx = tid & 63;
    int ty = tid >> 6;
    int row0 = blockIdx.x * 8 + ty * 4;

    // Label-width probe: int64 labels (<2^31) have all-zero high words.
    __shared__ int s_is64;
    if (tid == 0) s_is64 = 1;
    __syncthreads();
#pragma unroll 1
    for (int t = tid; t < M / 2; t += 128)
        if (lraw[2 * t + 1] != 0) s_is64 = 0;

    float qcx[4], qcy[4], qwz[4], qwh[4];
    float qx0[4], qy0[4], qx1[4], qy1[4], qa[4];
#pragma unroll
    for (int k = 0; k < 4; k++) {
        float4 bb = __ldg(boxes + row0 + k);
        qcx[k] = bb.x; qcy[k] = bb.y; qwz[k] = bb.z; qwh[k] = bb.w;
        float hw = 0.5f * bb.z, hh = 0.5f * bb.w;
        qx0[k] = bb.x - hw; qy0[k] = bb.y - hh;
        qx1[k] = bb.x + hw; qy1[k] = bb.y + hh;
        qa[k] = bb.z * bb.w;
    }
    __syncthreads();

    const float* sp = scores + row0 * C;
    float* op = out + (size_t)row0 * M + tx;
    const float4* tb = tboxes + tx;

    if (s_is64)
        cost_tile<1>(sp, op, tb, lraw + 2 * tx,
                     qcx, qcy, qwz, qwh, qx0, qy0, qx1, qy1, qa);
    else
        cost_tile<0>(sp, op, tb, lraw + tx,
                     qcx, qcy, qwz, qwh, qx0, qy0, qx1, qy1, qa);
}

// ---------------------------------------------------------------------------
// Generic fallback for unexpected shapes.
// ---------------------------------------------------------------------------
__global__ void __launch_bounds__(256)
cost_kernel(const float* __restrict__ scores,
            const float4* __restrict__ boxes,
            const float4* __restrict__ tboxes,
            float* __restrict__ out,
            int rows, int C, int m) {
    int tid = threadIdx.x;
    int tx = tid & 63;
    int ty = tid >> 6;
    int row0 = blockIdx.x * 16 + ty * 4;

    float qcx[4], qcy[4], qw[4], qh[4];
    float qx0[4], qy0[4], qx1[4], qy1[4], qa[4];
    const float* srow[4];
    float* orow[4];

#pragma unroll
    for (int k = 0; k < 4; k++) {
        int r = row0 + k;
        if (r > rows - 1) r = rows - 1;
        float4 bb = __ldg(boxes + r);
        qcx[k] = bb.x; qcy[k] = bb.y; qw[k] = bb.z; qh[k] = bb.w;
        float hw = 0.5f * bb.z, hh = 0.5f * bb.w;
        qx0[k] = bb.x - hw; qy0[k] = bb.y - hh;
        qx1[k] = bb.x + hw; qy1[k] = bb.y + hh;
        qa[k] = (qx1[k] - qx0[k]) * (qy1[k] - qy0[k]);
        srow[k] = scores + (size_t)r * C;
        orow[k] = out + (size_t)r * m + tx;
    }

    int nj = (m + 63) >> 6;
    for (int jj = 0; jj < nj; jj++) {
        int j = tx + (jj << 6);
        if (j >= m) break;
        float4 t  = __ldg(g_txyxy + j);
        float4 tc = __ldg(tboxes + j);
        float2 al = __ldg(g_tal + j);
        float ta = al.x;
        int lab = __float_as_int(al.y);

#pragma unroll
        for (int k = 0; k < 4; k++) {
            float sc = __ldg(srow[k] + lab);
            float l1 = fabsf(qcx[k] - tc.x) + fabsf(qcy[k] - tc.y)
                     + fabsf(qw[k] - tc.z) + fabsf(qh[k] - tc.w);
            float ltx = fmaxf(qx0[k], t.x), lty = fmaxf(qy0[k], t.y);
            float rbx = fminf(qx1[k], t.z), rby = fminf(qy1[k], t.w);
            float iw = fmaxf(rbx - ltx, 0.0f), ih = fmaxf(rby - lty, 0.0f);
            float inter = iw * ih;
            float uni = qa[k] + ta - inter;
            float ex0 = fminf(qx0[k], t.x), ey0 = fminf(qy0[k], t.y);
            float ex1 = fmaxf(qx1[k], t.z), ey1 = fmaxf(qy1[k], t.w);
            float ae = (ex1 - ex0) * (ey1 - ey0);
            float s = fmaf(uni, frcp(ae), inter * frcp(uni));
            float c = fmaf(5.0f, l1, 2.0f - sc);
            c = fmaf(-2.0f, s, c);
            orow[k][(size_t)(jj << 6)] = c;
        }
    }
}

extern "C" void kernel_launch(void* const* d_in, const int* in_sizes, int n_in,
                              void* d_out, int out_size) {
    const float* scores  = (const float*)d_in[0];
    const float4* boxes  = (const float4*)d_in[1];
    const int*   labraw  = (const int*)d_in[2];
    const float4* tboxes = (const float4*)d_in[3];
    float* out = (float*)d_out;

    int rows = in_sizes[1] / 4;      // b*n = 9600
    int m    = in_sizes[3] / 4;      // 1280
    int C    = in_sizes[0] / rows;   // 91

    if (C == 91 && m == 1280 && (rows % 8) == 0) {
        cost_kernel_fast<<<rows / 8, 128>>>(scores, boxes, labraw, tboxes, out);
    } else {
        setup_kernel<<<1, 512>>>(tboxes, labraw, m);
        int blocks = (rows + 15) / 16;
        cost_kernel<<<blocks, 256>>>(scores, boxes, tboxes, out, rows, C, m);
    }
}

// round 7
// speedup vs baseline: 1.1982x; 1.1982x over previous
#include <cuda_runtime.h>
#include <cstdint>

#define TMAX 1280

__device__ int g_lab[TMAX];        // fallback path only
__device__ float4 g_txyxy[TMAX];   // fallback path only
__device__ float2 g_tal[TMAX];     // fallback path only

__device__ __forceinline__ float frcp(float x) {
    float r;
    asm("rcp.approx.f32 %0, %1;" : "=f"(r) : "f"(x));
    return r;
}

// Fallback-path setup: label normalize + target xyxy/area precompute.
__global__ void setup_kernel(const float4* __restrict__ tboxes,
                             const int* __restrict__ lraw, int m) {
    __shared__ int is64;
    if (threadIdx.x == 0) is64 = 1;
    __syncthreads();
    for (int t = threadIdx.x; t < m / 2; t += blockDim.x)
        if (lraw[2 * t + 1] != 0) is64 = 0;
    __syncthreads();
    int f = is64;
    for (int j = threadIdx.x; j < m; j += blockDim.x) {
        int lab = f ? lraw[2 * j] : lraw[j];
        g_lab[j] = lab;
        float4 b = tboxes[j];
        float hw = 0.5f * b.z, hh = 0.5f * b.w;
        float4 t;
        t.x = b.x - hw; t.y = b.y - hh;
        t.z = b.x + hw; t.w = b.y + hh;
        g_txyxy[j] = t;
        float2 al;
        al.x = (t.z - t.x) * (t.w - t.y);
        al.y = __int_as_float(lab);
        g_tal[j] = al;
    }
}

// ---------------------------------------------------------------------------
// Fast-path tile body: 2 rows x 20 column steps per thread.
// Templated on label stride (SH=1: int64 source, SH=0: int32).
// Small live set (~45 regs) -> spill-free under a 51-reg cap.
// ---------------------------------------------------------------------------
template <int SH>
__device__ __forceinline__ void cost_tile2(
    const float* __restrict__ sp,        // scores + row0*C
    float* __restrict__ op,              // out + row0*M + tx
    const float4* __restrict__ tb,       // tboxes + tx
    const int* __restrict__ lp,          // lraw + (tx << SH)
    const float qcx[2], const float qcy[2],
    const float qwz[2], const float qwh[2],
    const float qx0[2], const float qy0[2],
    const float qx1[2], const float qy1[2])
{
    constexpr int C = 91;
    constexpr int M = 1280;

#pragma unroll 10
    for (int jj = 0; jj < 20; jj++) {
        float4 b = __ldg(tb + jj * 64);          // target cxcywh
        int lab = __ldg(lp + ((jj * 64) << SH)); // immediate-offset label
        float hw = 0.5f * b.z, hh = 0.5f * b.w;
        float tx0 = b.x - hw, ty0 = b.y - hh;
        float tx1 = b.x + hw, ty1 = b.y + hh;
        float ta = b.z * b.w;
        const float* sa = sp + lab;

        float scv[2];
#pragma unroll
        for (int k = 0; k < 2; k++) scv[k] = __ldg(sa + k * C);

#pragma unroll
        for (int k = 0; k < 2; k++) {
            // L1 on raw cxcywh (exact vs reference; abs folds into operands)
            float ux = qcx[k] - b.x, uy = qcy[k] - b.y;
            float vx = qwz[k] - b.z, vy = qwh[k] - b.w;
            float l1 = (fabsf(ux) + fabsf(uy)) + (fabsf(vx) + fabsf(vy));

            // signed per-dim overlap, reused for intersection and enclosure
            float ox = fminf(qx1[k], tx1) - fmaxf(qx0[k], tx0);
            float oy = fminf(qy1[k], ty1) - fmaxf(qy0[k], ty0);
            float iw = fmaxf(ox, 0.0f), ih = fmaxf(oy, 0.0f);
            float inter = iw * ih;

            // enclosing span = w + w' - signed_overlap
            float ew = (qwz[k] + b.z) - ox;
            float eh = (qwh[k] + b.w) - oy;
            float ae = ew * eh;

            float uni = fmaf(qwz[k], qwh[k], ta) - inter;

            // cost = 5*l1 + (2 - sc) - 2*(inter/uni + uni/ae)
            float s = fmaf(uni, frcp(ae), inter * frcp(uni));
            float c = fmaf(5.0f, l1, 2.0f - scv[k]);
            c = fmaf(-2.0f, s, c);

            op[k * M + jj * 64] = c;
        }
    }
}

// ---------------------------------------------------------------------------
// Fast path: C=91, M=1280, rows % 8 == 0. Single launch.
// 256-thr block = 4 groups x (2 rows x 64 lanes) = 8 rows; grid = rows/8.
// launch_bounds(256,5) -> 51-reg cap, 5 blocks/SM, 40 warps (62.5% occ).
// ---------------------------------------------------------------------------
__global__ void __launch_bounds__(256, 5)
cost_kernel_fast(const float* __restrict__ scores,
                 const float4* __restrict__ boxes,
                 const int* __restrict__ lraw,
                 const float4* __restrict__ tboxes,
                 float* __restrict__ out) {
    constexpr int C = 91;
    constexpr int M = 1280;

    int tid = threadIdx.x;
    int tx = tid & 63;
    int ty = tid >> 6;
    int row0 = blockIdx.x * 8 + ty * 2;

    // Label-width probe: int64 labels (<2^31) have all-zero high words.
    __shared__ int s_is64;
    if (tid == 0) s_is64 = 1;
    __syncthreads();
    {
        int any = 0;
#pragma unroll 1
        for (int t = tid; t < M / 2; t += 256)
            any |= lraw[2 * t + 1];
        if (any != 0) s_is64 = 0;
    }

    float qcx[2], qcy[2], qwz[2], qwh[2];
    float qx0[2], qy0[2], qx1[2], qy1[2];
#pragma unroll
    for (int k = 0; k < 2; k++) {
        float4 bb = __ldg(boxes + row0 + k);
        qcx[k] = bb.x; qcy[k] = bb.y; qwz[k] = bb.z; qwh[k] = bb.w;
        float hw = 0.5f * bb.z, hh = 0.5f * bb.w;
        qx0[k] = bb.x - hw; qy0[k] = bb.y - hh;
        qx1[k] = bb.x + hw; qy1[k] = bb.y + hh;
    }
    __syncthreads();

    const float* sp = scores + row0 * C;
    float* op = out + (size_t)row0 * M + tx;
    const float4* tb = tboxes + tx;

    if (s_is64)
        cost_tile2<1>(sp, op, tb, lraw + 2 * tx,
                      qcx, qcy, qwz, qwh, qx0, qy0, qx1, qy1);
    else
        cost_tile2<0>(sp, op, tb, lraw + tx,
                      qcx, qcy, qwz, qwh, qx0, qy0, qx1, qy1);
}

// ---------------------------------------------------------------------------
// Generic fallback for unexpected shapes.
// ---------------------------------------------------------------------------
__global__ void __launch_bounds__(256)
cost_kernel(const float* __restrict__ scores,
            const float4* __restrict__ boxes,
            const float4* __restrict__ tboxes,
            float* __restrict__ out,
            int rows, int C, int m) {
    int tid = threadIdx.x;
    int tx = tid & 63;
    int ty = tid >> 6;
    int row0 = blockIdx.x * 16 + ty * 4;

    float qcx[4], qcy[4], qw[4], qh[4];
    float qx0[4], qy0[4], qx1[4], qy1[4], qa[4];
    const float* srow[4];
    float* orow[4];

#pragma unroll
    for (int k = 0; k < 4; k++) {
        int r = row0 + k;
        if (r > rows - 1) r = rows - 1;
        float4 bb = __ldg(boxes + r);
        qcx[k] = bb.x; qcy[k] = bb.y; qw[k] = bb.z; qh[k] = bb.w;
        float hw = 0.5f * bb.z, hh = 0.5f * bb.w;
        qx0[k] = bb.x - hw; qy0[k] = bb.y - hh;
        qx1[k] = bb.x + hw; qy1[k] = bb.y + hh;
        qa[k] = (qx1[k] - qx0[k]) * (qy1[k] - qy0[k]);
        srow[k] = scores + (size_t)r * C;
        orow[k] = out + (size_t)r * m + tx;
    }

    int nj = (m + 63) >> 6;
    for (int jj = 0; jj < nj; jj++) {
        int j = tx + (jj << 6);
        if (j >= m) break;
        float4 t  = __ldg(g_txyxy + j);
        float4 tc = __ldg(tboxes + j);
        float2 al = __ldg(g_tal + j);
        float ta = al.x;
        int lab = __float_as_int(al.y);

#pragma unroll
        for (int k = 0; k < 4; k++) {
            float sc = __ldg(srow[k] + lab);
            float l1 = fabsf(qcx[k] - tc.x) + fabsf(qcy[k] - tc.y)
                     + fabsf(qw[k] - tc.z) + fabsf(qh[k] - tc.w);
            float ltx = fmaxf(qx0[k], t.x), lty = fmaxf(qy0[k], t.y);
            float rbx = fminf(qx1[k], t.z), rby = fminf(qy1[k], t.w);
            float iw = fmaxf(rbx - ltx, 0.0f), ih = fmaxf(rby - lty, 0.0f);
            float inter = iw * ih;
            float uni = qa[k] + ta - inter;
            float ex0 = fminf(qx0[k], t.x), ey0 = fminf(qy0[k], t.y);
            float ex1 = fmaxf(qx1[k], t.z), ey1 = fmaxf(qy1[k], t.w);
            float ae = (ex1 - ex0) * (ey1 - ey0);
            float s = fmaf(uni, frcp(ae), inter * frcp(uni));
            float c = fmaf(5.0f, l1, 2.0f - sc);
            c = fmaf(-2.0f, s, c);
            orow[k][(size_t)(jj << 6)] = c;
        }
    }
}

extern "C" void kernel_launch(void* const* d_in, const int* in_sizes, int n_in,
                              void* d_out, int out_size) {
    const float* scores  = (const float*)d_in[0];
    const float4* boxes  = (const float4*)d_in[1];
    const int*   labraw  = (const int*)d_in[2];
    const float4* tboxes = (const float4*)d_in[3];
    float* out = (float*)d_out;

    int rows = in_sizes[1] / 4;      // b*n = 9600
    int m    = in_sizes[3] / 4;      // 1280
    int C    = in_sizes[0] / rows;   // 91

    if (C == 91 && m == 1280 && (rows % 8) == 0) {
        cost_kernel_fast<<<rows / 8, 256>>>(scores, boxes, labraw, tboxes, out);
    } else {
        setup_kernel<<<1, 512>>>(tboxes, labraw, m);
        int blocks = (rows + 15) / 16;
        cost_kernel<<<blocks, 256>>>(scores, boxes, tboxes, out, rows, C, m);
    }
}